// round 8
// baseline (speedup 1.0000x reference)
#include <cuda_runtime.h>
#include <cuda_fp16.h>
#include <float.h>
#include <stdint.h>

// ---------------------------------------------------------------------------
// Problem constants
#define BB   32
#define CC   256
#define HWD  1024
#define KK   1024
#define NN   (BB * HWD)        // 32768
#define BM   64                // query rows per CTA
#define NCHUNK 64              // 8 nt * 2 bc(w-comp) * 4 kc

// SMEM layout (dynamic)
#define SM_A        0                   // 2 comps x [64 m][256 k] fp16 (swizzled) = 2*32768
#define SM_A_COMP   32768
#define SM_B        65536               // 2 bufs x [128 n][64 k] fp16 (swizzled) = 2*16384
#define SM_B_BUF    16384
#define SMEM_TOTAL  98304
// reduction overlays B region (B is dead by then)
#define SM_REDV     SM_B                // 64*4 floats
#define SM_REDI     (SM_B + 2048)       // 64*4 ints
#define SM_RIDX     (SM_B + 4096)       // 64 ints

// ---------------------------------------------------------------------------
// Device scratch (static globals — no allocation). 16B-aligned for cp.async.
__device__ __align__(256) __half g_wb[2][KK * CC];   // w comps [n][k]
__device__ __align__(256) __half g_zb[2][NN * CC];   // z comps [m][k]
__device__ float g_wsq[KK];

// ---------------------------------------------------------------------------
__device__ __forceinline__ uint32_t smem_u32(const void* p) {
    return (uint32_t)__cvta_generic_to_shared(p);
}
__device__ __forceinline__ void cpa16(uint32_t s, const void* g) {
    asm volatile("cp.async.cg.shared.global [%0], [%1], 16;\n" :: "r"(s), "l"(g));
}
#define CPA_COMMIT() asm volatile("cp.async.commit_group;\n" ::: "memory")
#define CPA_WAIT(n)  asm volatile("cp.async.wait_group %0;\n" :: "n"(n) : "memory")

__device__ __forceinline__ void ldsm4(uint32_t* r, uint32_t addr) {
    asm volatile("ldmatrix.sync.aligned.m8n8.x4.shared.b16 {%0,%1,%2,%3}, [%4];"
                 : "=r"(r[0]), "=r"(r[1]), "=r"(r[2]), "=r"(r[3]) : "r"(addr));
}
__device__ __forceinline__ void mma16816(float* d, const uint32_t* a,
                                         uint32_t b0, uint32_t b1) {
    asm volatile("mma.sync.aligned.m16n8k16.row.col.f32.f16.f16.f32 "
                 "{%0,%1,%2,%3}, {%4,%5,%6,%7}, {%8,%9}, {%0,%1,%2,%3};"
                 : "+f"(d[0]), "+f"(d[1]), "+f"(d[2]), "+f"(d[3])
                 : "r"(a[0]), "r"(a[1]), "r"(a[2]), "r"(a[3]), "r"(b0), "r"(b1));
}

// ---------------------------------------------------------------------------
// Prep: split w into 2 fp16 components
__global__ void split_w_kernel(const float* __restrict__ w) {
    int idx = blockIdx.x * 256 + threadIdx.x;
    float v = w[idx];
    __half h1 = __float2half_rn(v);
    float r1 = v - __half2float(h1);
    __half h2 = __float2half_rn(r1);
    g_wb[0][idx] = h1; g_wb[1][idx] = h2;
}

// ||e_k||^2 per code, one warp per code (exact fp32)
__global__ void wsq_kernel(const float* __restrict__ w) {
    int code = blockIdx.x * 8 + (threadIdx.x >> 5);
    int lane = threadIdx.x & 31;
    const float* row = w + (size_t)code * CC;
    float s = 0.f;
    #pragma unroll
    for (int c = lane; c < CC; c += 32) { float v = row[c]; s += v * v; }
    #pragma unroll
    for (int o = 16; o; o >>= 1) s += __shfl_down_sync(0xffffffffu, s, o);
    if (lane == 0) g_wsq[code] = s;
}

// Split + transpose z: z[b][c][hw] -> g_zb[comp][m = b*1024+hw][c]
__global__ void split_z_kernel(const float* __restrict__ z) {
    __shared__ float t[32][33];
    int c0  = blockIdx.x * 32;
    int hw0 = blockIdx.y * 32;
    int b   = blockIdx.z;
    int x = threadIdx.x, y0 = threadIdx.y;     // 32 x 8
    const float* zb = z + ((size_t)b * CC) * HWD;
    #pragma unroll
    for (int yy = 0; yy < 32; yy += 8)
        t[y0 + yy][x] = zb[(size_t)(c0 + y0 + yy) * HWD + hw0 + x];
    __syncthreads();
    #pragma unroll
    for (int yy = 0; yy < 32; yy += 8) {
        int hwl = y0 + yy;
        float v = t[x][hwl];
        size_t o = (size_t)(b * HWD + hw0 + hwl) * CC + c0 + x;
        __half h1 = __float2half_rn(v);
        float r1 = v - __half2float(h1);
        __half h2 = __float2half_rn(r1);
        g_zb[0][o] = h1; g_zb[1][o] = h2;
    }
}

// ---------------------------------------------------------------------------
// B chunk loader: chunk c = nt*8 + bc*4 + kc -> [128 n][64 k] fp16, swizzled
__device__ __forceinline__ void load_b_chunk(uint32_t Bbase, int c, int buf, int tid) {
    int nt = c >> 3, pos = c & 7, bc = pos >> 2, kc = pos & 3;
    const __half* base = g_wb[bc] + ((size_t)(nt * 128) << 8) + (kc << 6);
    uint32_t dst = Bbase + buf * SM_B_BUF;
    #pragma unroll
    for (int j = 0; j < 2; ++j) {
        int gi = j * 512 + tid;            // 0..1023 granules
        int r = gi >> 3, g = gi & 7;
        cpa16(dst + r * 128 + ((g ^ (r & 7)) << 4),
              base + ((size_t)r << 8) + (g << 3));
    }
}

// ---------------------------------------------------------------------------
// Fused HMMA GEMM + argmin + gather + write. 512 threads, 2 CTA/SM.
// Warp grid 4(m) x 4(n); warp tile 16m x 32n.
__global__ __launch_bounds__(512, 2)
void vq_kernel(const float* __restrict__ z,
               const float* __restrict__ w,
               float* __restrict__ out) {
    extern __shared__ __align__(1024) char smem[];
    const int tid  = threadIdx.x;
    const int lane = tid & 31;
    const int wid  = tid >> 5;
    const int wm   = wid >> 2;     // 0..3 : m-warp (16 rows each)
    const int wn   = wid & 3;      // 0..3 : n-warp (32 cols each)

    const int n0  = blockIdx.x * BM;
    const int b   = n0 >> 10;
    const int hw0 = n0 & (HWD - 1);

    const uint32_t sbase = smem_u32(smem);
    const uint32_t Abase = sbase + SM_A;
    const uint32_t Bbase = sbase + SM_B;

    // ---- prologue: resident A (2 comps) + B chunk 0, one cp.async group ----
    #pragma unroll
    for (int j = 0; j < 8; ++j) {
        int gi = j * 512 + tid;            // 0..4095 granules
        int comp = gi >> 11;
        int rem  = gi & 2047;
        int m = rem >> 5, g = rem & 31;
        cpa16(Abase + comp * SM_A_COMP + m * 512 + ((g ^ (m & 7)) << 4),
              g_zb[comp] + ((size_t)(n0 + m) << 8) + (g << 3));
    }
    load_b_chunk(Bbase, 0, 0, tid);
    CPA_COMMIT();

    // per-thread ldmatrix address components
    const uint32_t a_row = wm * 16 + (lane & 15);
    const uint32_t a_ghi = lane >> 4;
    const uint32_t a_rx  = a_row & 7;
    const uint32_t a_addr0 = Abase + a_row * 512;

    uint32_t b_addr0[2], b_gx[2];                      // per bl(16n)
    #pragma unroll
    for (int bl = 0; bl < 2; ++bl) {
        uint32_t nr = wn * 32 + bl * 16 + (lane & 15);
        b_addr0[bl] = Bbase + nr * 128;
        b_gx[bl] = nr & 7;
    }

    float acc[4][4];
    float bestv[2];
    int   besti[2];
    #pragma unroll
    for (int i = 0; i < 2; ++i) { bestv[i] = FLT_MAX; besti[i] = 0; }

    // ---- main loop over 64 chunks ----
    for (int c = 0; c < NCHUNK; ++c) {
        const int nt  = c >> 3;
        const int pos = c & 7;
        const int bc  = pos >> 2;
        const int kc  = pos & 3;
        const int buf = c & 1;
        const int nac = 2 - bc;    // w1:{x1,x2}  w2:{x1}

        if (c + 1 < NCHUNK) {
            load_b_chunk(Bbase, c + 1, buf ^ 1, tid);
            CPA_COMMIT();
            CPA_WAIT(1);
        } else {
            CPA_WAIT(0);
        }
        __syncthreads();

        if (pos == 0) {
            #pragma unroll
            for (int j = 0; j < 4; ++j)
                #pragma unroll
                for (int d = 0; d < 4; ++d) acc[j][d] = 0.f;
        }

        // compute: 4 k-steps of 16 within the 64k chunk
        #pragma unroll
        for (int kh = 0; kh < 2; ++kh) {
            #pragma unroll
            for (int ks2 = 0; ks2 < 2; ++ks2) {
                const int ks = kh * 2 + ks2;
                uint32_t bfr[2][4];
                #pragma unroll
                for (int bl = 0; bl < 2; ++bl) {
                    uint32_t g = ks * 2 + a_ghi;
                    ldsm4(bfr[bl],
                          b_addr0[bl] + buf * SM_B_BUF + ((g ^ b_gx[bl]) << 4));
                }
                for (int ac = 0; ac < nac; ++ac) {
                    uint32_t g = kc * 8 + ks * 2 + a_ghi;
                    uint32_t afr[4];
                    ldsm4(afr, a_addr0 + ac * SM_A_COMP + ((g ^ a_rx) << 4));
                    #pragma unroll
                    for (int bl = 0; bl < 2; ++bl) {
                        mma16816(acc[bl * 2],     afr, bfr[bl][0], bfr[bl][2]);
                        mma16816(acc[bl * 2 + 1], afr, bfr[bl][1], bfr[bl][3]);
                    }
                }
            }
        }

        // fold argmin once the n-tile's full-K accumulation is complete
        if (pos == 7) {
            int nb = nt * 128 + wn * 32 + ((lane & 3) << 1);
            #pragma unroll
            for (int nf = 0; nf < 4; ++nf) {
                int nidx = nb + nf * 8;
                float w0 = __ldg(&g_wsq[nidx]);
                float w1 = __ldg(&g_wsq[nidx + 1]);
                float s;
                s = w0 - 2.f * acc[nf][0];
                if (s < bestv[0]) { bestv[0] = s; besti[0] = nidx; }
                s = w1 - 2.f * acc[nf][1];
                if (s < bestv[0]) { bestv[0] = s; besti[0] = nidx + 1; }
                s = w0 - 2.f * acc[nf][2];
                if (s < bestv[1]) { bestv[1] = s; besti[1] = nidx; }
                s = w1 - 2.f * acc[nf][3];
                if (s < bestv[1]) { bestv[1] = s; besti[1] = nidx + 1; }
            }
        }
        __syncthreads();
    }

    // ---- argmin reduce: across 4 lanes sharing rows, then across 4 n-warps ----
    float* redv = (float*)(smem + SM_REDV);
    int*   redi = (int*)(smem + SM_REDI);
    int*   ridx = (int*)(smem + SM_RIDX);
    #pragma unroll
    for (int slot = 0; slot < 2; ++slot) {
        float v = bestv[slot];
        int  id = besti[slot];
        #pragma unroll
        for (int m = 1; m <= 2; m <<= 1) {
            float ov = __shfl_xor_sync(0xffffffffu, v, m);
            int   oi = __shfl_xor_sync(0xffffffffu, id, m);
            if (ov < v || (ov == v && oi < id)) { v = ov; id = oi; }
        }
        if ((lane & 3) == 0) {
            int row = wm * 16 + (lane >> 2) + slot * 8;
            redv[row * 4 + wn] = v;
            redi[row * 4 + wn] = id;
        }
    }
    __syncthreads();
    if (tid < BM) {
        float v = redv[tid * 4];
        int  id = redi[tid * 4];
        #pragma unroll
        for (int j = 1; j < 4; ++j) {
            float ov = redv[tid * 4 + j];
            int   oi = redi[tid * 4 + j];
            if (ov < v || (ov == v && oi < id)) { v = ov; id = oi; }
        }
        ridx[tid] = id;
    }
    __syncthreads();

    // ---- output epilogue: gather q into smem (overlay A), write both outputs ----
    float* qs = (float*)(smem + SM_A);       // [256 c][64 m] fp32 = 64KB
    {
        int m = tid & 63;
        int cpart = tid >> 6;                // 0..7 (c eighths of 32)
        const float4* wr = (const float4*)(w + (size_t)ridx[m] * CC + cpart * 32);
        #pragma unroll
        for (int g = 0; g < 8; ++g) {
            float4 v = wr[g];
            int cq = cpart * 32 + g * 4;
            qs[(cq + 0) * BM + m] = v.x;
            qs[(cq + 1) * BM + m] = v.y;
            qs[(cq + 2) * BM + m] = v.z;
            qs[(cq + 3) * BM + m] = v.w;
        }
    }
    __syncthreads();
    {
        float* out_codes = out;
        float* out_bar   = out + (size_t)NN * CC;
        const int cg = tid >> 4;             // 0..31
        const int r4 = (tid & 15) * 4;       // 0..60
        #pragma unroll 4
        for (int cc = 0; cc < 8; ++cc) {
            int cq = cc * 32 + cg;
            size_t zo = ((size_t)(b * CC + cq)) * HWD + hw0 + r4;
            float4 zv = *(const float4*)(z + zo);
            float4 q  = *(const float4*)(qs + cq * BM + r4);
            float4 co;
            co.x = zv.x + (q.x - zv.x);
            co.y = zv.y + (q.y - zv.y);
            co.z = zv.z + (q.z - zv.z);
            co.w = zv.w + (q.w - zv.w);
            *(float4*)(out_codes + zo) = co;
            *(float4*)(out_bar   + zo) = q;
        }
    }
}

// ---------------------------------------------------------------------------
extern "C" void kernel_launch(void* const* d_in, const int* in_sizes, int n_in,
                              void* d_out, int out_size) {
    const float* z = (const float*)d_in[0];
    const float* w = (const float*)d_in[1];
    if (n_in >= 2 && in_sizes[0] == KK * CC && in_sizes[1] == NN * CC) {
        const float* t = z; z = w; w = t;
    }
    float* out = (float*)d_out;

    static bool attr_set = false;
    if (!attr_set) {
        cudaFuncSetAttribute(vq_kernel, cudaFuncAttributeMaxDynamicSharedMemorySize,
                             SMEM_TOTAL);
        attr_set = true;
    }

    split_w_kernel<<<KK * CC / 256, 256>>>(w);
    wsq_kernel<<<KK / 8, 256>>>(w);
    split_z_kernel<<<dim3(CC / 32, HWD / 32, BB), dim3(32, 8)>>>(z);
    vq_kernel<<<NN / BM, 512, SMEM_TOTAL>>>(z, w, out);
}

// round 9
// speedup vs baseline: 1.1024x; 1.1024x over previous
#include <cuda_runtime.h>
#include <cuda_fp16.h>
#include <float.h>
#include <stdint.h>

// ---------------------------------------------------------------------------
// Problem constants
#define BB   32
#define CC   256
#define HWD  1024
#define KK   1024
#define NN   (BB * HWD)        // 32768
#define BM   128               // query rows per CTA
#define NCHUNK 64              // 8 nt * 2 bc(w-comp) * 4 kc

// SMEM layout (dynamic)
#define SM_A        0                   // 2 comps x [128 m][256 k] fp16 (swizzled) = 2*65536
#define SM_A_COMP   65536
#define SM_B        131072              // 4 stages x [128 n][64 k] fp16 (swizzled) = 4*16384
#define SM_B_BUF    16384
#define SMEM_TOTAL  196608
// reduction overlays B region (B is dead by then)
#define SM_REDV     SM_B                // 128*4 floats
#define SM_REDI     (SM_B + 2048)       // 128*4 ints
#define SM_RIDX     (SM_B + 4096)       // 128 ints

// ---------------------------------------------------------------------------
// Device scratch (static globals — no allocation). 16B-aligned for cp.async.
__device__ __align__(256) __half g_wb[2][KK * CC];   // w comps [n][k]
__device__ __align__(256) __half g_zb[2][NN * CC];   // z comps [m][k]
__device__ float g_wsq[KK];

// ---------------------------------------------------------------------------
__device__ __forceinline__ uint32_t smem_u32(const void* p) {
    return (uint32_t)__cvta_generic_to_shared(p);
}
__device__ __forceinline__ void cpa16(uint32_t s, const void* g) {
    asm volatile("cp.async.cg.shared.global [%0], [%1], 16;\n" :: "r"(s), "l"(g));
}
#define CPA_COMMIT() asm volatile("cp.async.commit_group;\n" ::: "memory")
#define CPA_WAIT(n)  asm volatile("cp.async.wait_group %0;\n" :: "n"(n) : "memory")

__device__ __forceinline__ void ldsm4(uint32_t* r, uint32_t addr) {
    asm volatile("ldmatrix.sync.aligned.m8n8.x4.shared.b16 {%0,%1,%2,%3}, [%4];"
                 : "=r"(r[0]), "=r"(r[1]), "=r"(r[2]), "=r"(r[3]) : "r"(addr));
}
__device__ __forceinline__ void mma16816(float* d, const uint32_t* a,
                                         uint32_t b0, uint32_t b1) {
    asm volatile("mma.sync.aligned.m16n8k16.row.col.f32.f16.f16.f32 "
                 "{%0,%1,%2,%3}, {%4,%5,%6,%7}, {%8,%9}, {%0,%1,%2,%3};"
                 : "+f"(d[0]), "+f"(d[1]), "+f"(d[2]), "+f"(d[3])
                 : "r"(a[0]), "r"(a[1]), "r"(a[2]), "r"(a[3]), "r"(b0), "r"(b1));
}

// ---------------------------------------------------------------------------
// Prep: split w into 2 fp16 components
__global__ void split_w_kernel(const float* __restrict__ w) {
    int idx = blockIdx.x * 256 + threadIdx.x;
    float v = w[idx];
    __half h1 = __float2half_rn(v);
    float r1 = v - __half2float(h1);
    __half h2 = __float2half_rn(r1);
    g_wb[0][idx] = h1; g_wb[1][idx] = h2;
}

// ||e_k||^2 per code, one warp per code (exact fp32)
__global__ void wsq_kernel(const float* __restrict__ w) {
    int code = blockIdx.x * 8 + (threadIdx.x >> 5);
    int lane = threadIdx.x & 31;
    const float* row = w + (size_t)code * CC;
    float s = 0.f;
    #pragma unroll
    for (int c = lane; c < CC; c += 32) { float v = row[c]; s += v * v; }
    #pragma unroll
    for (int o = 16; o; o >>= 1) s += __shfl_down_sync(0xffffffffu, s, o);
    if (lane == 0) g_wsq[code] = s;
}

// Split + transpose z: z[b][c][hw] -> g_zb[comp][m = b*1024+hw][c]
__global__ void split_z_kernel(const float* __restrict__ z) {
    __shared__ float t[32][33];
    int c0  = blockIdx.x * 32;
    int hw0 = blockIdx.y * 32;
    int b   = blockIdx.z;
    int x = threadIdx.x, y0 = threadIdx.y;     // 32 x 8
    const float* zb = z + ((size_t)b * CC) * HWD;
    #pragma unroll
    for (int yy = 0; yy < 32; yy += 8)
        t[y0 + yy][x] = zb[(size_t)(c0 + y0 + yy) * HWD + hw0 + x];
    __syncthreads();
    #pragma unroll
    for (int yy = 0; yy < 32; yy += 8) {
        int hwl = y0 + yy;
        float v = t[x][hwl];
        size_t o = (size_t)(b * HWD + hw0 + hwl) * CC + c0 + x;
        __half h1 = __float2half_rn(v);
        float r1 = v - __half2float(h1);
        __half h2 = __float2half_rn(r1);
        g_zb[0][o] = h1; g_zb[1][o] = h2;
    }
}

// ---------------------------------------------------------------------------
// B chunk loader: chunk c = nt*8 + bc*4 + kc -> [128 n][64 k] fp16, swizzled
__device__ __forceinline__ void load_b_chunk(uint32_t Bbase, int c, int slot, int tid) {
    int nt = c >> 3, pos = c & 7, bc = pos >> 2, kc = pos & 3;
    const __half* base = g_wb[bc] + ((size_t)(nt * 128) << 8) + (kc << 6);
    uint32_t dst = Bbase + slot * SM_B_BUF;
    #pragma unroll
    for (int j = 0; j < 2; ++j) {
        int gi = j * 512 + tid;            // 0..1023 granules
        int r = gi >> 3, g = gi & 7;
        cpa16(dst + r * 128 + ((g ^ (r & 7)) << 4),
              base + ((size_t)r << 8) + (g << 3));
    }
}

// ---------------------------------------------------------------------------
// Fused HMMA GEMM + argmin + gather + write. 512 threads, 1 CTA/SM.
// Warp grid 4(m) x 4(n); warp tile 32m x 32n. 4-stage B ring, 1 barrier/chunk.
__global__ __launch_bounds__(512, 1)
void vq_kernel(const float* __restrict__ z,
               const float* __restrict__ w,
               float* __restrict__ out) {
    extern __shared__ __align__(1024) char smem[];
    const int tid  = threadIdx.x;
    const int lane = tid & 31;
    const int wid  = tid >> 5;
    const int wm   = wid >> 2;     // 0..3 : m-warp (32 rows each)
    const int wn   = wid & 3;      // 0..3 : n-warp (32 cols each)

    const int n0  = blockIdx.x * BM;
    const int b   = n0 >> 10;
    const int hw0 = n0 & (HWD - 1);

    const uint32_t sbase = smem_u32(smem);
    const uint32_t Abase = sbase + SM_A;
    const uint32_t Bbase = sbase + SM_B;

    // ---- prologue: group0 = {A (2 comps), B chunk 0}; group1 = c1; group2 = c2 ----
    #pragma unroll
    for (int j = 0; j < 16; ++j) {
        int gi = j * 512 + tid;            // 0..8191 granules
        int comp = gi >> 12;
        int rem  = gi & 4095;
        int m = rem >> 5, g = rem & 31;
        cpa16(Abase + comp * SM_A_COMP + m * 512 + ((g ^ (m & 7)) << 4),
              g_zb[comp] + ((size_t)(n0 + m) << 8) + (g << 3));
    }
    load_b_chunk(Bbase, 0, 0, tid);
    CPA_COMMIT();
    load_b_chunk(Bbase, 1, 1, tid);
    CPA_COMMIT();
    load_b_chunk(Bbase, 2, 2, tid);
    CPA_COMMIT();

    // per-thread ldmatrix address components
    const uint32_t a_row = wm * 32 + (lane & 15);
    const uint32_t a_ghi = lane >> 4;
    const uint32_t a_rx  = a_row & 7;
    const uint32_t a_addr0 = Abase + a_row * 512;     // + ac*65536 + mf*8192 + gsw*16

    uint32_t b_addr0[2], b_gx[2];                      // per bl(16n)
    #pragma unroll
    for (int bl = 0; bl < 2; ++bl) {
        uint32_t nr = wn * 32 + bl * 16 + (lane & 15);
        b_addr0[bl] = Bbase + nr * 128;
        b_gx[bl] = nr & 7;
    }

    float acc[2][4][4];
    float bestv[4];
    int   besti[4];
    #pragma unroll
    for (int i = 0; i < 4; ++i) { bestv[i] = FLT_MAX; besti[i] = 0; }

    // ---- main loop over 64 chunks; ONE barrier per chunk ----
    for (int c = 0; c < NCHUNK; ++c) {
        const int nt   = c >> 3;
        const int pos  = c & 7;
        const int bc   = pos >> 2;
        const int kc   = pos & 3;
        const int slot = c & 3;
        const int nac  = 2 - bc;    // w1:{x1,x2}  w2:{x1}

        // 1) own group for chunk c complete (groups c+1, c+2 may remain pending)
        if (c + 2 < NCHUNK)      CPA_WAIT(2);
        else if (c + 1 < NCHUNK) CPA_WAIT(1);
        else                     CPA_WAIT(0);
        // 2) all threads' chunk-c data visible; slot (c-1)&3 fully consumed
        __syncthreads();
        // 3) prefetch chunk c+3 into the just-freed slot
        if (c + 3 < NCHUNK) {
            load_b_chunk(Bbase, c + 3, (c + 3) & 3, tid);
            CPA_COMMIT();
        }

        if (pos == 0) {
            #pragma unroll
            for (int i = 0; i < 2; ++i)
                #pragma unroll
                for (int j = 0; j < 4; ++j)
                    #pragma unroll
                    for (int d = 0; d < 4; ++d) acc[i][j][d] = 0.f;
        }

        // 4) compute: two k-halves of the 64k chunk
        #pragma unroll
        for (int kh = 0; kh < 2; ++kh) {
            uint32_t bfr[2][2][4];
            #pragma unroll
            for (int ks2 = 0; ks2 < 2; ++ks2) {
                int ks = kh * 2 + ks2;
                #pragma unroll
                for (int bl = 0; bl < 2; ++bl) {
                    uint32_t g = ks * 2 + a_ghi;
                    ldsm4(bfr[ks2][bl],
                          b_addr0[bl] + slot * SM_B_BUF + ((g ^ b_gx[bl]) << 4));
                }
            }
            for (int ac = 0; ac < nac; ++ac) {
                #pragma unroll
                for (int ks2 = 0; ks2 < 2; ++ks2) {
                    int ks = kh * 2 + ks2;
                    uint32_t g = kc * 8 + ks * 2 + a_ghi;
                    uint32_t off = ((g ^ a_rx) << 4);
                    uint32_t afr[2][4];
                    ldsm4(afr[0], a_addr0 + ac * SM_A_COMP + off);
                    ldsm4(afr[1], a_addr0 + ac * SM_A_COMP + 8192 + off);
                    #pragma unroll
                    for (int mf = 0; mf < 2; ++mf)
                        #pragma unroll
                        for (int bl = 0; bl < 2; ++bl) {
                            mma16816(acc[mf][bl * 2],     afr[mf],
                                     bfr[ks2][bl][0], bfr[ks2][bl][2]);
                            mma16816(acc[mf][bl * 2 + 1], afr[mf],
                                     bfr[ks2][bl][1], bfr[ks2][bl][3]);
                        }
                }
            }
        }

        // 5) fold argmin once the n-tile's full-K accumulation is complete
        if (pos == 7) {
            int nb = nt * 128 + wn * 32 + ((lane & 3) << 1);
            #pragma unroll
            for (int mf = 0; mf < 2; ++mf)
                #pragma unroll
                for (int nf = 0; nf < 4; ++nf) {
                    int nidx = nb + nf * 8;
                    float w0 = __ldg(&g_wsq[nidx]);
                    float w1 = __ldg(&g_wsq[nidx + 1]);
                    float s;
                    s = w0 - 2.f * acc[mf][nf][0];
                    if (s < bestv[mf*2])   { bestv[mf*2]   = s; besti[mf*2]   = nidx; }
                    s = w1 - 2.f * acc[mf][nf][1];
                    if (s < bestv[mf*2])   { bestv[mf*2]   = s; besti[mf*2]   = nidx + 1; }
                    s = w0 - 2.f * acc[mf][nf][2];
                    if (s < bestv[mf*2+1]) { bestv[mf*2+1] = s; besti[mf*2+1] = nidx; }
                    s = w1 - 2.f * acc[mf][nf][3];
                    if (s < bestv[mf*2+1]) { bestv[mf*2+1] = s; besti[mf*2+1] = nidx + 1; }
                }
        }
    }
    __syncthreads();   // B ring dead; safe to overlay reductions

    // ---- argmin reduce: across 4 lanes sharing rows, then across 4 n-warps ----
    float* redv = (float*)(smem + SM_REDV);
    int*   redi = (int*)(smem + SM_REDI);
    int*   ridx = (int*)(smem + SM_RIDX);
    #pragma unroll
    for (int slot = 0; slot < 4; ++slot) {
        float v = bestv[slot];
        int  id = besti[slot];
        #pragma unroll
        for (int m = 1; m <= 2; m <<= 1) {
            float ov = __shfl_xor_sync(0xffffffffu, v, m);
            int   oi = __shfl_xor_sync(0xffffffffu, id, m);
            if (ov < v || (ov == v && oi < id)) { v = ov; id = oi; }
        }
        if ((lane & 3) == 0) {
            int row = wm * 32 + (slot >> 1) * 16 + (lane >> 2) + ((slot & 1) << 3);
            redv[row * 4 + wn] = v;
            redi[row * 4 + wn] = id;
        }
    }
    __syncthreads();
    if (tid < BM) {
        float v = redv[tid * 4];
        int  id = redi[tid * 4];
        #pragma unroll
        for (int j = 1; j < 4; ++j) {
            float ov = redv[tid * 4 + j];
            int   oi = redi[tid * 4 + j];
            if (ov < v || (ov == v && oi < id)) { v = ov; id = oi; }
        }
        ridx[tid] = id;
    }
    __syncthreads();

    // ---- output epilogue: gather q into smem (overlay A), write both outputs ----
    float* qs = (float*)(smem + SM_A);       // [256 c][128 m] fp32
    {
        int m = tid & 127;
        int cpart = tid >> 7;                // 0..3 (c quarters)
        const float4* wr = (const float4*)(w + (size_t)ridx[m] * CC + cpart * 64);
        #pragma unroll
        for (int g = 0; g < 16; ++g) {
            float4 v = wr[g];
            int cq = cpart * 64 + g * 4;
            qs[(cq + 0) * BM + m] = v.x;
            qs[(cq + 1) * BM + m] = v.y;
            qs[(cq + 2) * BM + m] = v.z;
            qs[(cq + 3) * BM + m] = v.w;
        }
    }
    __syncthreads();
    {
        float* out_codes = out;
        float* out_bar   = out + (size_t)NN * CC;
        const int cg = tid >> 5;             // 0..15
        const int r4 = (tid & 31) * 4;
        #pragma unroll 4
        for (int cc = 0; cc < 16; ++cc) {
            int cq = cg * 16 + cc;
            size_t zo = ((size_t)(b * CC + cq)) * HWD + hw0 + r4;
            float4 zv = *(const float4*)(z + zo);
            float4 q  = *(const float4*)(qs + cq * BM + r4);
            float4 co;
            co.x = zv.x + (q.x - zv.x);
            co.y = zv.y + (q.y - zv.y);
            co.z = zv.z + (q.z - zv.z);
            co.w = zv.w + (q.w - zv.w);
            *(float4*)(out_codes + zo) = co;
            *(float4*)(out_bar   + zo) = q;
        }
    }
}

// ---------------------------------------------------------------------------
extern "C" void kernel_launch(void* const* d_in, const int* in_sizes, int n_in,
                              void* d_out, int out_size) {
    const float* z = (const float*)d_in[0];
    const float* w = (const float*)d_in[1];
    if (n_in >= 2 && in_sizes[0] == KK * CC && in_sizes[1] == NN * CC) {
        const float* t = z; z = w; w = t;
    }
    float* out = (float*)d_out;

    static bool attr_set = false;
    if (!attr_set) {
        cudaFuncSetAttribute(vq_kernel, cudaFuncAttributeMaxDynamicSharedMemorySize,
                             SMEM_TOTAL);
        attr_set = true;
    }

    split_w_kernel<<<KK * CC / 256, 256>>>(w);
    wsq_kernel<<<KK / 8, 256>>>(w);
    split_z_kernel<<<dim3(CC / 32, HWD / 32, BB), dim3(32, 8)>>>(z);
    vq_kernel<<<NN / BM, 512, SMEM_TOTAL>>>(z, w, out);
}

// round 10
// speedup vs baseline: 1.5048x; 1.3650x over previous
#include <cuda_runtime.h>
#include <cuda_fp16.h>
#include <float.h>
#include <stdint.h>

// ---------------------------------------------------------------------------
#define BB   32
#define CC   256
#define HWD  1024
#define KK   1024
#define NN   (BB * HWD)        // 32768
#define BM   128               // query rows per CTA
#define NCHUNK 32              // 8 nt * 4 kc (single product)

// SMEM layout for GEMM kernel
#define SM_A        0                   // [128 m][256 k] fp16 swizzled = 65536
#define SM_B        65536               // 4 stages x [128 n][64 k] fp16 = 65536
#define SM_B_BUF    16384
#define SM_SS       131072              // score staging half[128][136] = 34816
#define SS_PITCH    136
#define SMEM_TOTAL  (131072 + 128 * SS_PITCH * 2)   // 165888
#define EPI_SMEM    (CC * BM * 4)                   // 131072

// ---------------------------------------------------------------------------
// Device scratch (static globals — no allocation)
__device__ __align__(256) __half g_w1[KK * CC];          // w fp16 [n][k]
__device__ __align__(256) __half g_z1[NN * CC];          // z fp16 [m][k]
__device__ __align__(256) float  g_zt[NN * CC];          // z fp32 [m][c] (exact copy)
__device__ __align__(256) __half g_scores[(size_t)NN * KK];  // raw dots, fp16
__device__ float2 g_tab[KK];                             // {wsq, err_slope}
__device__ int    g_ridx[NN];

// ---------------------------------------------------------------------------
__device__ __forceinline__ uint32_t smem_u32(const void* p) {
    return (uint32_t)__cvta_generic_to_shared(p);
}
__device__ __forceinline__ void cpa16(uint32_t s, const void* g) {
    asm volatile("cp.async.cg.shared.global [%0], [%1], 16;\n" :: "r"(s), "l"(g));
}
#define CPA_COMMIT() asm volatile("cp.async.commit_group;\n" ::: "memory")
#define CPA_WAIT(n)  asm volatile("cp.async.wait_group %0;\n" :: "n"(n) : "memory")

__device__ __forceinline__ void ldsm4(uint32_t* r, uint32_t addr) {
    asm volatile("ldmatrix.sync.aligned.m8n8.x4.shared.b16 {%0,%1,%2,%3}, [%4];"
                 : "=r"(r[0]), "=r"(r[1]), "=r"(r[2]), "=r"(r[3]) : "r"(addr));
}
__device__ __forceinline__ void mma16816(float* d, const uint32_t* a,
                                         uint32_t b0, uint32_t b1) {
    asm volatile("mma.sync.aligned.m16n8k16.row.col.f32.f16.f16.f32 "
                 "{%0,%1,%2,%3}, {%4,%5,%6,%7}, {%8,%9}, {%0,%1,%2,%3};"
                 : "+f"(d[0]), "+f"(d[1]), "+f"(d[2]), "+f"(d[3])
                 : "r"(a[0]), "r"(a[1]), "r"(a[2]), "r"(a[3]), "r"(b0), "r"(b1));
}

// ---------------------------------------------------------------------------
// Prep: w -> fp16
__global__ void split_w_kernel(const float* __restrict__ w) {
    int idx = blockIdx.x * 256 + threadIdx.x;
    g_w1[idx] = __float2half_rn(w[idx]);
}

// Per-code ||w||^2 and certified error slope. One warp per code.
__global__ void tab_kernel(const float* __restrict__ w) {
    int code = blockIdx.x * 8 + (threadIdx.x >> 5);
    int lane = threadIdx.x & 31;
    const float* row = w + (size_t)code * CC;
    float s = 0.f;
    #pragma unroll
    for (int c = lane; c < CC; c += 32) { float v = row[c]; s += v * v; }
    #pragma unroll
    for (int o = 16; o; o >>= 1) s += __shfl_down_sync(0xffffffffu, s, o);
    if (lane == 0) g_tab[code] = make_float2(s, 0.0035f * sqrtf(s));
}

// Transpose z: z[b][c][hw] -> g_z1 fp16 [m][c] and g_zt fp32 [m][c]
__global__ void zprep_kernel(const float* __restrict__ z) {
    __shared__ float t[32][33];
    int c0  = blockIdx.x * 32;
    int hw0 = blockIdx.y * 32;
    int b   = blockIdx.z;
    int x = threadIdx.x, y0 = threadIdx.y;     // 32 x 8
    const float* zb = z + ((size_t)b * CC) * HWD;
    #pragma unroll
    for (int yy = 0; yy < 32; yy += 8)
        t[y0 + yy][x] = zb[(size_t)(c0 + y0 + yy) * HWD + hw0 + x];
    __syncthreads();
    #pragma unroll
    for (int yy = 0; yy < 32; yy += 8) {
        int hwl = y0 + yy;
        float v = t[x][hwl];
        size_t o = (size_t)(b * HWD + hw0 + hwl) * CC + c0 + x;
        g_zt[o] = v;
        g_z1[o] = __float2half_rn(v);
    }
}

// ---------------------------------------------------------------------------
// B chunk loader: chunk c = nt*4 + kc -> [128 n][64 k] fp16, swizzled
__device__ __forceinline__ void load_b_chunk(uint32_t Bbase, int c, int slot, int tid) {
    int nt = c >> 2, kc = c & 3;
    const __half* base = g_w1 + ((size_t)(nt * 128) << 8) + (kc << 6);
    uint32_t dst = Bbase + slot * SM_B_BUF;
    #pragma unroll
    for (int j = 0; j < 2; ++j) {
        int gi = j * 512 + tid;
        int r = gi >> 3, g = gi & 7;
        cpa16(dst + r * 128 + ((g ^ (r & 7)) << 4),
              base + ((size_t)r << 8) + (g << 3));
    }
}

// ---------------------------------------------------------------------------
// 1-product HMMA GEMM, streams raw dot products to g_scores (fp16).
__global__ __launch_bounds__(512, 1)
void vq_gemm_kernel() {
    extern __shared__ __align__(1024) char smem[];
    const int tid  = threadIdx.x;
    const int lane = tid & 31;
    const int wid  = tid >> 5;
    const int wm   = wid >> 2;     // m-warp (32 rows)
    const int wn   = wid & 3;      // n-warp (32 cols)

    const int n0 = blockIdx.x * BM;

    const uint32_t sbase = smem_u32(smem);
    const uint32_t Abase = sbase + SM_A;
    const uint32_t Bbase = sbase + SM_B;

    // prologue: A resident + B chunks 0..2
    #pragma unroll
    for (int j = 0; j < 8; ++j) {
        int gi = j * 512 + tid;            // 4096 granules
        int m = gi >> 5, g = gi & 31;
        cpa16(Abase + m * 512 + ((g ^ (m & 7)) << 4),
              g_z1 + ((size_t)(n0 + m) << 8) + (g << 3));
    }
    load_b_chunk(Bbase, 0, 0, tid);
    CPA_COMMIT();
    load_b_chunk(Bbase, 1, 1, tid);
    CPA_COMMIT();
    load_b_chunk(Bbase, 2, 2, tid);
    CPA_COMMIT();

    const uint32_t a_row = wm * 32 + (lane & 15);
    const uint32_t a_ghi = lane >> 4;
    const uint32_t a_rx  = a_row & 7;
    const uint32_t a_addr0 = Abase + a_row * 512;

    uint32_t b_addr0[2], b_gx[2];
    #pragma unroll
    for (int bl = 0; bl < 2; ++bl) {
        uint32_t nr = wn * 32 + bl * 16 + (lane & 15);
        b_addr0[bl] = Bbase + nr * 128;
        b_gx[bl] = nr & 7;
    }

    float acc[2][4][4];

    for (int c = 0; c < NCHUNK; ++c) {
        const int nt   = c >> 2;
        const int kc   = c & 3;
        const int slot = c & 3;

        if (c + 2 < NCHUNK)      CPA_WAIT(2);
        else if (c + 1 < NCHUNK) CPA_WAIT(1);
        else                     CPA_WAIT(0);
        __syncthreads();
        if (c + 3 < NCHUNK) {
            load_b_chunk(Bbase, c + 3, (c + 3) & 3, tid);
            CPA_COMMIT();
        }

        if (kc == 0) {
            #pragma unroll
            for (int i = 0; i < 2; ++i)
                #pragma unroll
                for (int j = 0; j < 4; ++j)
                    #pragma unroll
                    for (int d = 0; d < 4; ++d) acc[i][j][d] = 0.f;
        }

        #pragma unroll
        for (int kh = 0; kh < 2; ++kh) {
            #pragma unroll
            for (int ks2 = 0; ks2 < 2; ++ks2) {
                const int ks = kh * 2 + ks2;
                uint32_t bfr[2][4];
                #pragma unroll
                for (int bl = 0; bl < 2; ++bl) {
                    uint32_t g = ks * 2 + a_ghi;
                    ldsm4(bfr[bl], b_addr0[bl] + slot * SM_B_BUF + ((g ^ b_gx[bl]) << 4));
                }
                uint32_t g = kc * 8 + ks * 2 + a_ghi;
                uint32_t off = ((g ^ a_rx) << 4);
                uint32_t afr[2][4];
                ldsm4(afr[0], a_addr0 + off);
                ldsm4(afr[1], a_addr0 + 8192 + off);
                #pragma unroll
                for (int mf = 0; mf < 2; ++mf)
                    #pragma unroll
                    for (int bl = 0; bl < 2; ++bl) {
                        mma16816(acc[mf][bl * 2],     afr[mf], bfr[bl][0], bfr[bl][2]);
                        mma16816(acc[mf][bl * 2 + 1], afr[mf], bfr[bl][1], bfr[bl][3]);
                    }
            }
        }

        // after the n-tile's full K: stage fp16 dots in smem, then coalesced store
        if (kc == 3) {
            __half* ss = (__half*)(smem + SM_SS);
            int r0  = wm * 32 + (lane >> 2);
            int col0 = wn * 32 + ((lane & 3) << 1);
            #pragma unroll
            for (int mf = 0; mf < 2; ++mf)
                #pragma unroll
                for (int nf = 0; nf < 4; ++nf) {
                    int r = r0 + mf * 16;
                    int col = col0 + nf * 8;
                    *(__half2*)&ss[r * SS_PITCH + col] =
                        __floats2half2_rn(acc[mf][nf][0], acc[mf][nf][1]);
                    *(__half2*)&ss[(r + 8) * SS_PITCH + col] =
                        __floats2half2_rn(acc[mf][nf][2], acc[mf][nf][3]);
                }
            __syncthreads();
            {
                int r = tid >> 2, part = tid & 3;
                const uint4* src = (const uint4*)(smem + SM_SS + r * (SS_PITCH * 2) + part * 64);
                uint4* dst = (uint4*)(g_scores + (((size_t)(n0 + r)) << 10) + (nt << 7) + part * 32);
                #pragma unroll
                for (int j = 0; j < 4; ++j) dst[j] = src[j];
            }
        }
    }
}

// ---------------------------------------------------------------------------
// Certified argmin: per-row candidate window + exact fp32 rescore.
__global__ __launch_bounds__(256)
void select_kernel(const float* __restrict__ w) {
    const int lane = threadIdx.x & 31;
    const int m = blockIdx.x * 8 + (threadIdx.x >> 5);

    // z row (exact fp32) + row norm bound
    float zv[8]; float xsq = 0.f;
    const float* zr = g_zt + ((size_t)m << 8);
    #pragma unroll
    for (int j = 0; j < 8; ++j) { zv[j] = zr[j * 32 + lane]; xsq += zv[j] * zv[j]; }
    #pragma unroll
    for (int o = 16; o; o >>= 1) xsq += __shfl_xor_sync(0xffffffffu, xsq, o);
    const float xn = sqrtf(xsq) * 1.0001f + 0.01f;

    const uint32_t* sp = (const uint32_t*)(g_scores + ((size_t)m << 10));
    uint32_t sv[16];
    #pragma unroll
    for (int i = 0; i < 16; ++i) sv[i] = sp[i * 32 + lane];

    // T = min over codes of upper bound
    float T = FLT_MAX;
    #pragma unroll
    for (int i = 0; i < 16; ++i) {
        int k0 = (i * 32 + lane) * 2;
        float4 tb = *(const float4*)&g_tab[k0];     // wsq0, sb0, wsq1, sb1
        __half2 h = *(__half2*)&sv[i];
        float s0 = tb.x - 2.f * __half2float(h.x);
        float s1 = tb.z - 2.f * __half2float(h.y);
        T = fminf(T, fminf(s0 + xn * tb.y + 0.2f, s1 + xn * tb.w + 0.2f));
    }
    #pragma unroll
    for (int o = 16; o; o >>= 1) T = fminf(T, __shfl_xor_sync(0xffffffffu, T, o));

    // candidates: lower bound <= T; rescore each exactly in fp32
    float best = FLT_MAX; int bi = 0x7fffffff;
    #pragma unroll
    for (int i = 0; i < 16; ++i) {
        int k0 = (i * 32 + lane) * 2;
        float4 tb = *(const float4*)&g_tab[k0];
        __half2 h = *(__half2*)&sv[i];
        float s0 = tb.x - 2.f * __half2float(h.x);
        float s1 = tb.z - 2.f * __half2float(h.y);
        bool c0 = (s0 - xn * tb.y - 0.2f) <= T;
        bool c1 = (s1 - xn * tb.w - 0.2f) <= T;
        #pragma unroll
        for (int half = 0; half < 2; ++half) {
            uint32_t mk = __ballot_sync(0xffffffffu, half ? c1 : c0);
            while (mk) {
                int src = __ffs(mk) - 1; mk &= mk - 1;
                int k = __shfl_sync(0xffffffffu, k0, src) + half;
                float dot = 0.f;
                const float* wr = w + ((size_t)k << 8);
                #pragma unroll
                for (int j = 0; j < 8; ++j)
                    dot = fmaf(zv[j], __ldg(&wr[j * 32 + lane]), dot);
                #pragma unroll
                for (int o = 16; o; o >>= 1) dot += __shfl_xor_sync(0xffffffffu, dot, o);
                float se = __ldg(&g_tab[k].x) - 2.f * dot;
                if (se < best || (se == best && k < bi)) { best = se; bi = k; }
            }
        }
    }
    if (lane == 0) g_ridx[m] = bi;
}

// ---------------------------------------------------------------------------
// Output epilogue: gather w[ridx], write codes (= z + (q - z)) and codes_bar.
__global__ __launch_bounds__(512)
void epilogue_kernel(const float* __restrict__ z, const float* __restrict__ w,
                     float* __restrict__ out) {
    extern __shared__ float qs[];       // [256 c][128 m]
    const int tid = threadIdx.x;
    const int n0  = blockIdx.x * BM;
    const int b   = n0 >> 10;
    const int hw0 = n0 & (HWD - 1);

    {
        int m = tid & 127, cpart = tid >> 7;   // 0..3 (64-c quarters)
        const float4* wr = (const float4*)(w + ((size_t)g_ridx[n0 + m] << 8) + cpart * 64);
        #pragma unroll
        for (int g = 0; g < 16; ++g) {
            float4 v = wr[g];
            int cq = cpart * 64 + g * 4;
            qs[(cq + 0) * BM + m] = v.x;
            qs[(cq + 1) * BM + m] = v.y;
            qs[(cq + 2) * BM + m] = v.z;
            qs[(cq + 3) * BM + m] = v.w;
        }
    }
    __syncthreads();
    {
        float* out_bar = out + (size_t)NN * CC;
        const int cg = tid >> 5;               // 0..15
        const int r4 = (tid & 31) * 4;
        #pragma unroll 4
        for (int cc = 0; cc < 16; ++cc) {
            int cq = cg * 16 + cc;
            size_t zo = ((size_t)(b * CC + cq)) * HWD + hw0 + r4;
            float4 zvv = *(const float4*)(z + zo);
            float4 q   = *(const float4*)(qs + cq * BM + r4);
            float4 co;
            co.x = zvv.x + (q.x - zvv.x);
            co.y = zvv.y + (q.y - zvv.y);
            co.z = zvv.z + (q.z - zvv.z);
            co.w = zvv.w + (q.w - zvv.w);
            *(float4*)(out + zo)     = co;
            *(float4*)(out_bar + zo) = q;
        }
    }
}

// ---------------------------------------------------------------------------
extern "C" void kernel_launch(void* const* d_in, const int* in_sizes, int n_in,
                              void* d_out, int out_size) {
    const float* z = (const float*)d_in[0];
    const float* w = (const float*)d_in[1];
    if (n_in >= 2 && in_sizes[0] == KK * CC && in_sizes[1] == NN * CC) {
        const float* t = z; z = w; w = t;
    }
    float* out = (float*)d_out;

    static bool attr_set = false;
    if (!attr_set) {
        cudaFuncSetAttribute(vq_gemm_kernel, cudaFuncAttributeMaxDynamicSharedMemorySize,
                             SMEM_TOTAL);
        cudaFuncSetAttribute(epilogue_kernel, cudaFuncAttributeMaxDynamicSharedMemorySize,
                             EPI_SMEM);
        attr_set = true;
    }

    split_w_kernel<<<KK * CC / 256, 256>>>(w);
    tab_kernel<<<KK / 8, 256>>>(w);
    zprep_kernel<<<dim3(CC / 32, HWD / 32, BB), dim3(32, 8)>>>(z);
    vq_gemm_kernel<<<NN / BM, 512, SMEM_TOTAL>>>();
    select_kernel<<<NN / 8, 256>>>(w);
    epilogue_kernel<<<NN / BM, 512, EPI_SMEM>>>(z, w, out);
}